// round 15
// baseline (speedup 1.0000x reference)
#include <cuda_runtime.h>
#include <math_constants.h>

// Problem constants (fixed by the dataset)
#define B_      128
#define L_I     2
#define L_Q     10
#define N_ACT   8
#define IM      64
#define IMP     66
#define NPIX    4096
#define NTHR    512
#define TILE    32           // output rows per CTA
#define TILES   2
#define INROWS  36           // TILE + 4 halo rows staged
#define ISTR    72           // in_s row stride; data cols 4..67, zero cols 3 & 68
#define RROWS   34           // TILE + 2 r rows

#define Q_ELEMS   (B_ * L_Q * NPIX)       // 5242880
#define LOGIT_OFF Q_ELEMS
#define ACT_OFF   (Q_ELEMS + B_ * N_ACT)  // 5243904

// ---- grid-wide argmax state (self-resetting each launch -> graph-replay safe) ----
__device__ unsigned long long g_best  = 0ULL;
__device__ unsigned int       g_count = 0u;

// slow-path (w != 0) scratch — never touched on the fast path
__device__ float g_r  [B_][IMP * IMP];
__device__ float g_qr [B_][L_Q][NPIX];
__device__ float g_vb [2][B_][IMP * IMP];

__device__ __forceinline__ unsigned int ordered_f32(float f) {
    unsigned int u = __float_as_uint(f);
    return (u & 0x80000000u) ? ~u : (u | 0x80000000u);
}

// logits from qv[10], write to out, contribute to grid argmax. One thread calls.
__device__ __forceinline__ void logits_and_argmax(const float* qv, const float* fc_s,
                                                  float* out, int b) {
    float best = -CUDART_INF_F;
    int   bi   = 0;
    #pragma unroll
    for (int a = 0; a < N_ACT; a++) {
        float s = 0.f;
        #pragma unroll
        for (int o = 0; o < L_Q; o++) s += fc_s[a * L_Q + o] * qv[o];
        out[LOGIT_OFF + b * N_ACT + a] = s;
        if (s > best) { best = s; bi = b * N_ACT + a; }   // strict > keeps first
    }
    const unsigned long long key =
        ((unsigned long long)ordered_f32(best) << 32) |
        (unsigned long long)(0xFFFFFFFFu - (unsigned int)bi);
    atomicMax(&g_best, key);
    __threadfence();
    const unsigned int cnt = atomicAdd(&g_count, 1u);
    if (cnt == B_ - 1u) {                 // exactly B_ contributors grid-wide
        const unsigned long long k2 = atomicMax(&g_best, 0ULL);   // atomic read
        const unsigned int flat = 0xFFFFFFFFu - (unsigned int)(k2 & 0xFFFFFFFFu);
        out[ACT_OFF] = (float)flat;
        g_best = 0ULL;
        __threadfence();
        atomicExch(&g_count, 0u);
    }
}

__global__ __launch_bounds__(NTHR, 2)
void vin_kernel(const float* __restrict__ in,
                const int*   __restrict__ sx_,
                const int*   __restrict__ sy_,
                const int*   __restrict__ kptr,   // may be null
                const float* __restrict__ h_w,
                const float* __restrict__ h_b,
                const float* __restrict__ r_w,
                const float* __restrict__ q_w,
                const float* __restrict__ w,
                const float* __restrict__ fc_w,
                float* __restrict__ out)
{
    __shared__ float in_s[L_I][INROWS][ISTR];            // 5184 floats, halo-padded
    __shared__ __align__(16) float hw_s[2700];           // h_w staging (dead after S1)
    __shared__ float rw_s[150];
    __shared__ float hb_s[150];
    __shared__ float r_s[RROWS][IMP];                    // rows gx0-1..gx0+32; cols 0/65 zero
    __shared__ float qw_s[90];
    __shared__ float ww_s[90];
    __shared__ float fc_s[80];
    __shared__ float weffb[20];                          // [0..17]=weff, [18]=beff

    const int tile = blockIdx.x;
    const int b    = blockIdx.y;
    const int gx0  = tile * TILE;
    const int tid  = threadIdx.x;

    // ================ S0: stage everything coalesced (max MLP, no deps) =============
    {   // input rows gx0-2..gx0+33 (OOB -> 0): 1152 float4
        const float4* inb4 = (const float4*)(in + (size_t)b * L_I * NPIX);
        #pragma unroll
        for (int i = 0; i < 3; i++) {
            const int e = tid + i * NTHR;                 // 0..1535
            if (e < L_I * INROWS * (IM / 4)) {
                const int ch  = e / (INROWS * (IM / 4));
                const int rem = e - ch * (INROWS * (IM / 4));
                const int row = rem >> 4, c4 = rem & 15;
                const int gr  = gx0 - 2 + row;
                float4 v = make_float4(0.f, 0.f, 0.f, 0.f);
                if (gr >= 0 && gr < IM) v = inb4[ch * (NPIX / 4) + gr * 16 + c4];
                *(float4*)&in_s[ch][row][4 + 4 * c4] = v;
            }
        }
    }
    {   // h_w: 675 float4, coalesced, 2 rounds
        const float4* hw4 = (const float4*)h_w;
        float4* dst = (float4*)hw_s;
        #pragma unroll
        for (int i = 0; i < 2; i++) {
            const int e = tid + i * NTHR;
            if (e < 675) dst[e] = hw4[e];
        }
    }
    if (tid < 150) { rw_s[tid] = r_w[tid]; hb_s[tid] = h_b[tid]; }
    if (tid < 90)  { qw_s[tid] = q_w[tid]; ww_s[tid] = w[tid]; }
    if (tid < 80)  fc_s[tid] = fc_w[tid];
    if (tid < 144) {   // in_s col halos (indices 3 and 68): 2ch * 36rows * 2
        const int ch = tid / 72, rr = (tid % 72) >> 1, c = 3 + (tid & 1) * 65;
        in_s[ch][rr][c] = 0.f;
    } else if (tid < 144 + 68) {  // r_s col halos (0 and 65): 34rows * 2
        const int idx = tid - 144;
        r_s[idx >> 1][(idx & 1) * 65] = 0.f;
    }
    __syncthreads();   // sync1: staging visible

    // ================ S1: weight collapse from smem (16 lanes per item) =============
    // weff[j] = sum_c rw[c] * hw[18c + j]  (j=0..17),  beff = sum_c rw[c]*hb[c]
    {
        const int item = tid >> 4;        // 0..31 (only 0..18 meaningful)
        const int l    = tid & 15;
        float acc = 0.f;
        if (item < 18) {
            #pragma unroll
            for (int s = 0; s < 10; s++) {
                const int c = l + 16 * s;
                if (c < 150) acc += rw_s[c] * hw_s[18 * c + item];
            }
        } else if (item == 18) {
            #pragma unroll
            for (int s = 0; s < 10; s++) {
                const int c = l + 16 * s;
                if (c < 150) acc += rw_s[c] * hb_s[c];
            }
        }
        acc += __shfl_xor_sync(0xFFFFFFFFu, acc, 8);
        acc += __shfl_xor_sync(0xFFFFFFFFu, acc, 4);
        acc += __shfl_xor_sync(0xFFFFFFFFu, acc, 2);
        acc += __shfl_xor_sync(0xFFFFFFFFu, acc, 1);
        if (l == 0 && item < 19) weffb[item] = acc;
    }
    const int nz = (tid < 90) ? (ww_s[tid] != 0.f) : 0;
    const int f  = __syncthreads_or(nz);   // sync2: weffb ready, flag uniform

    // ====== S2: r-conv, consecutive-y mapping (conflict-free), unconditional LDS ====
    {
        float wr[18];
        #pragma unroll
        for (int j = 0; j < 18; j++) wr[j] = weffb[j];
        const float be = weffb[18];
        #pragma unroll
        for (int i = 0; i < 5; i++) {                     // 2176 px total
            const int e = tid + i * NTHR;
            if (e < RROWS * IM) {
                const int rx = e >> 6, y = e & 63;        // y consecutive within warp
                const int gr = gx0 - 1 + rx;
                float acc = be;
                #pragma unroll
                for (int ci = 0; ci < L_I; ci++)
                    #pragma unroll
                    for (int kh = 0; kh < 3; kh++)
                        #pragma unroll
                        for (int kw = 0; kw < 3; kw++)
                            acc += in_s[ci][rx + kh][y + kw + 3] * wr[ci * 9 + kh * 3 + kw];
                r_s[rx][y + 1] = (gr >= 0 && gr < IM) ? acc : 0.f;
            }
        }
    }
    __syncthreads();   // sync3: r_s ready

    float* outb = out + (size_t)b * L_Q * NPIX;

    if (!f) {
        // ============ FAST PATH (R9 q-conv shape): q == conv(r, q_w) ================
        const int row = tid >> 4;            // 0..31 (tile row)
        const int y0  = (tid & 15) * 4;      // 0,4,...,60
        float wnd[3][6];                     // r_s rows row..row+2, cols y0..y0+5
        #pragma unroll
        for (int kh = 0; kh < 3; kh++) {
            #pragma unroll
            for (int m = 0; m < 3; m++) {
                const float2 v = *(const float2*)&r_s[row + kh][y0 + 2 * m];
                wnd[kh][2 * m]     = v.x;
                wnd[kh][2 * m + 1] = v.y;
            }
        }
        float* obase = outb + (gx0 + row) * IM + y0;
        #pragma unroll
        for (int chk = 0; chk < 5; chk++) {      // 2 output channels per chunk
            float qa[18];
            #pragma unroll
            for (int j = 0; j < 18; j++) qa[j] = qw_s[chk * 18 + j];
            float a0[4], a1[4];
            #pragma unroll
            for (int px = 0; px < 4; px++) {
                float s0 = 0.f, s1 = 0.f;
                #pragma unroll
                for (int kh = 0; kh < 3; kh++)
                    #pragma unroll
                    for (int kw = 0; kw < 3; kw++) {
                        const float t = wnd[kh][px + kw];
                        s0 += t * qa[kh * 3 + kw];
                        s1 += t * qa[9 + kh * 3 + kw];
                    }
                a0[px] = s0; a1[px] = s1;
            }
            *(float4*)(obase + (2 * chk)     * NPIX) = make_float4(a0[0], a0[1], a0[2], a0[3]);
            *(float4*)(obase + (2 * chk + 1) * NPIX) = make_float4(a1[0], a1[1], a1[2], a1[3]);
        }
        // gather + logits + argmax: only the CTA whose rows contain sx
        if (tid == 0) {
            const int sx = sx_[b];
            if (sx >= gx0 && sx < gx0 + TILE) {
                const int sy = sy_[b];
                float qv[L_Q];
                #pragma unroll
                for (int oc = 0; oc < L_Q; oc++) {
                    float a = 0.f;
                    #pragma unroll
                    for (int kh = 0; kh < 3; kh++)
                        #pragma unroll
                        for (int kw = 0; kw < 3; kw++)
                            a += r_s[sx - gx0 + kh][sy + kw] * qw_s[oc * 9 + kh * 3 + kw];
                    qv[oc] = a;
                }
                logits_and_argmax(qv, fc_s, out, b);
            }
        }
        return;
    }

    // ================== SLOW PATH: w != 0, full k-iteration (tile 0 only) ==========
    if (tile != 0) return;
    {
        const int kk = (kptr != nullptr) ? *kptr : 40;
        const float* inb = in + (size_t)b * L_I * NPIX;

        for (int i = tid; i < IMP * IMP; i += NTHR) {
            g_r[b][i] = 0.f; g_vb[0][b][i] = 0.f; g_vb[1][b][i] = 0.f;
        }
        __syncthreads();

        // full-image r (weights from smem; cold path, perf irrelevant)
        for (int e = tid; e < NPIX; e += NTHR) {
            const int x = e >> 6, y = e & 63;
            float acc = weffb[18];
            for (int ci = 0; ci < L_I; ci++)
                for (int kh = 0; kh < 3; kh++) {
                    const int ix = x + kh - 1;
                    if (ix < 0 || ix >= IM) continue;
                    for (int kw = 0; kw < 3; kw++) {
                        const int iy = y + kw - 1;
                        if (iy < 0 || iy >= IM) continue;
                        acc += inb[ci * NPIX + ix * IM + iy] * weffb[ci * 9 + kh * 3 + kw];
                    }
                }
            g_r[b][(x + 1) * IMP + y + 1] = acc;
        }
        __syncthreads();

        // qr + v0
        for (int e = tid; e < NPIX; e += NTHR) {
            const int x = e >> 6, y = e & 63;
            float t[9];
            for (int kh = 0; kh < 3; kh++)
                for (int kw = 0; kw < 3; kw++)
                    t[kh * 3 + kw] = g_r[b][(x + kh) * IMP + y + kw];
            float vmax = -CUDART_INF_F;
            for (int oc = 0; oc < L_Q; oc++) {
                float a = 0.f;
                for (int j = 0; j < 9; j++) a += t[j] * qw_s[oc * 9 + j];
                g_qr[b][oc][e] = a;
                vmax = fmaxf(vmax, a);
            }
            g_vb[0][b][(x + 1) * IMP + y + 1] = vmax;
        }
        __syncthreads();

        int cur = 0;
        for (int it = 0; it < kk - 1; it++) {
            for (int e = tid; e < NPIX; e += NTHR) {
                const int x = e >> 6, y = e & 63;
                float t[9];
                for (int kh = 0; kh < 3; kh++)
                    for (int kw = 0; kw < 3; kw++)
                        t[kh * 3 + kw] = g_vb[cur][b][(x + kh) * IMP + y + kw];
                float vmax = -CUDART_INF_F;
                for (int oc = 0; oc < L_Q; oc++) {
                    float a = g_qr[b][oc][e];
                    for (int j = 0; j < 9; j++) a += t[j] * ww_s[oc * 9 + j];
                    vmax = fmaxf(vmax, a);
                }
                g_vb[cur ^ 1][b][(x + 1) * IMP + y + 1] = vmax;
            }
            cur ^= 1;
            __syncthreads();
        }

        // final q = qr + conv(v, w)
        for (int e = tid; e < NPIX; e += NTHR) {
            const int x = e >> 6, y = e & 63;
            float t[9];
            for (int kh = 0; kh < 3; kh++)
                for (int kw = 0; kw < 3; kw++)
                    t[kh * 3 + kw] = g_vb[cur][b][(x + kh) * IMP + y + kw];
            for (int oc = 0; oc < L_Q; oc++) {
                float a = g_qr[b][oc][e];
                for (int j = 0; j < 9; j++) a += t[j] * ww_s[oc * 9 + j];
                outb[oc * NPIX + e] = a;
            }
        }
        __syncthreads();

        if (tid == 0) {
            const int sx = sx_[b], sy = sy_[b];
            float qv[L_Q];
            for (int oc = 0; oc < L_Q; oc++) {
                float a = g_qr[b][oc][sx * IM + sy];
                for (int kh = 0; kh < 3; kh++)
                    for (int kw = 0; kw < 3; kw++)
                        a += g_vb[cur][b][(sx + kh) * IMP + sy + kw]
                             * ww_s[oc * 9 + kh * 3 + kw];
                qv[oc] = a;
            }
            logits_and_argmax(qv, fc_s, out, b);
        }
    }
}

extern "C" void kernel_launch(void* const* d_in, const int* in_sizes, int n_in,
                              void* d_out, int out_size)
{
    // Inputs: input_view, state_x, state_y, [k], h_w, h_b, r_w, q_w, w, fc_w
    int hw_idx = -1;
    for (int i = 0; i < n_in; i++) {
        if (in_sizes[i] == 2700) { hw_idx = i; break; }
    }
    if (hw_idx < 0) hw_idx = 4;

    const float* in_v = (const float*)d_in[0];
    const int*   sx   = (const int*)d_in[1];
    const int*   sy   = (const int*)d_in[2];
    const int*   kptr = (hw_idx == 4) ? (const int*)d_in[3] : nullptr;
    const float* h_w  = (const float*)d_in[hw_idx];
    const float* h_b  = (const float*)d_in[hw_idx + 1];
    const float* r_w  = (const float*)d_in[hw_idx + 2];
    const float* q_w  = (const float*)d_in[hw_idx + 3];
    const float* w    = (const float*)d_in[hw_idx + 4];
    const float* fc_w = (const float*)d_in[hw_idx + 5];
    float* out = (float*)d_out;

    dim3 grid(TILES, B_);
    vin_kernel<<<grid, NTHR>>>(in_v, sx, sy, kptr, h_w, h_b, r_w,
                               q_w, w, fc_w, out);
}